// round 3
// baseline (speedup 1.0000x reference)
#include <cuda_runtime.h>
#include <cstdint>
#include <cstddef>

#define DI __device__ __forceinline__

static const int D_DIM = 512;   // embedding dim (fixed for this problem)
#define MAXN 32768
#define MAXK 1024

// Force precise libdevice log regardless of -use_fast_math (XLA uses __nv_logf;
// argmax selection requires bitwise-identical gumbel values).
extern "C" __device__ float __nv_logf(float);

// Scratch (device globals: no allocation allowed in kernel_launch)
__device__ float g_x[(size_t)MAXN * D_DIM];     //  64 MB combined normalized input
__device__ float g_cn[(size_t)MAXK * D_DIM];    //   2 MB normalized codebook
__device__ float g_l1[(size_t)MAXN * MAXK];     // 128 MB sim + gumbel(key1)  (argmax path)
__device__ float g_l2[(size_t)MAXN * MAXK];     // 128 MB sim + gumbel(key2)  (softmax path)

// ---------------------------------------------------------------------------
// Threefry-2x32 (exact JAX implementation)
// ---------------------------------------------------------------------------
__host__ __device__ inline uint32_t rotl32(uint32_t x, int r) {
    return (x << r) | (x >> (32 - r));
}

__host__ __device__ inline void threefry2x32(uint32_t k0, uint32_t k1,
                                             uint32_t& x0, uint32_t& x1) {
    uint32_t k2 = k0 ^ k1 ^ 0x1BD11BDAu;
    x0 += k0; x1 += k1;
#define TFR(r) { x0 += x1; x1 = rotl32(x1, r); x1 ^= x0; }
    TFR(13) TFR(15) TFR(26) TFR(6)
    x0 += k1; x1 += k2 + 1u;
    TFR(17) TFR(29) TFR(16) TFR(24)
    x0 += k2; x1 += k0 + 2u;
    TFR(13) TFR(15) TFR(26) TFR(6)
    x0 += k0; x1 += k1 + 3u;
    TFR(17) TFR(29) TFR(16) TFR(24)
    x0 += k1; x1 += k2 + 4u;
    TFR(13) TFR(15) TFR(26) TFR(6)
    x0 += k2; x1 += k0 + 5u;
#undef TFR
}

// JAX partitionable mode, 32-bit random bits for element index i (< 2^32):
//   (o0, o1) = threefry(key, x0 = hi64(i) = 0, x1 = lo64(i) = i);  bits = o0 ^ o1
DI uint32_t tf_bits(uint32_t k0, uint32_t k1, uint32_t i) {
    uint32_t x0 = 0u, x1 = i;
    threefry2x32(k0, k1, x0, x1);
    return x0 ^ x1;
}

// JAX: uniform(minval=tiny,maxval=1) -> gumbel = -log(-log(u)); bitwise libdevice log
DI float gumbel_from_bits(uint32_t bits) {
    float u = __uint_as_float((bits >> 9) | 0x3f800000u) - 1.0f;
    const float TINY = 1.17549435e-38f;
    float r = fmaxf(TINY, u + TINY);
    return -__nv_logf(-__nv_logf(r));
}

// ---------------------------------------------------------------------------
// Packed fp32x2 FMA helpers (sm_100+ PTX; ptxas never auto-emits FFMA2)
// ---------------------------------------------------------------------------
typedef unsigned long long u64;
DI u64 pk2(float lo, float hi) {
    u64 r; asm("mov.b64 %0, {%1,%2};" : "=l"(r) : "f"(lo), "f"(hi)); return r;
}
DI void upk2(u64 p, float& lo, float& hi) {
    asm("mov.b64 {%0,%1}, %2;" : "=f"(lo), "=f"(hi) : "l"(p));
}
DI u64 fma2(u64 a, u64 b, u64 c) {
    u64 d; asm("fma.rn.f32x2 %0, %1, %2, %3;" : "=l"(d) : "l"(a), "l"(b), "l"(c));
    return d;
}

// ---------------------------------------------------------------------------
// Kernel 1: normalize codebook rows -> g_cn
// ---------------------------------------------------------------------------
__global__ void norm_cb_kernel(const float* __restrict__ cb) {
    int r = blockIdx.x, t = threadIdx.x;   // 128 threads, D=512 -> 4/thread
    const float* row = cb + (size_t)r * D_DIM;
    float v[4]; float ss = 0.f;
#pragma unroll
    for (int i = 0; i < 4; i++) { v[i] = row[t + i * 128]; ss += v[i] * v[i]; }
    __shared__ float s4[4];
    for (int o = 16; o; o >>= 1) ss += __shfl_down_sync(0xffffffffu, ss, o);
    if ((t & 31) == 0) s4[t >> 5] = ss;
    __syncthreads();
    float nrm = fmaxf(sqrtf(s4[0] + s4[1] + s4[2] + s4[3]), 1e-8f);
    float* orow = g_cn + (size_t)r * D_DIM;
#pragma unroll
    for (int i = 0; i < 4; i++) orow[t + i * 128] = v[i] / nrm;
}

// ---------------------------------------------------------------------------
// Kernel 2: x = 0.5*state/||state|| + 0.5*adv/||adv|| -> g_x
// ---------------------------------------------------------------------------
__global__ void combine_kernel(const float* __restrict__ st,
                               const float* __restrict__ ad) {
    int r = blockIdx.x, t = threadIdx.x;
    const float* s = st + (size_t)r * D_DIM;
    const float* a = ad + (size_t)r * D_DIM;
    float sv[4], av[4]; float ssum = 0.f, asum = 0.f;
#pragma unroll
    for (int i = 0; i < 4; i++) {
        sv[i] = s[t + i * 128]; ssum += sv[i] * sv[i];
        av[i] = a[t + i * 128]; asum += av[i] * av[i];
    }
    __shared__ float s4[4], a4[4];
    for (int o = 16; o; o >>= 1) {
        ssum += __shfl_down_sync(0xffffffffu, ssum, o);
        asum += __shfl_down_sync(0xffffffffu, asum, o);
    }
    if ((t & 31) == 0) { s4[t >> 5] = ssum; a4[t >> 5] = asum; }
    __syncthreads();
    float ns = fmaxf(sqrtf(s4[0] + s4[1] + s4[2] + s4[3]), 1e-8f);
    float na = fmaxf(sqrtf(a4[0] + a4[1] + a4[2] + a4[3]), 1e-8f);
    float* x = g_x + (size_t)r * D_DIM;
#pragma unroll
    for (int i = 0; i < 4; i++)
        x[t + i * 128] = 0.5f * (sv[i] / ns) + 0.5f * (av[i] / na);
}

// ---------------------------------------------------------------------------
// Kernel 3: fp32 NT-GEMM (packed f32x2 FMA) fused with gumbel generation.
//   sim[m,k] = sum_d g_x[m,d] * g_cn[k,d]
//   epilogue: l1 = sim + gumbel(key1, m*K+k); l2 = sim + gumbel(key2, m*K+k)
//   128x128 tile, BK=16, 256 threads. Split 4+4 fragments (16B lane stride)
//   for conflict-free LDS.128. Threefry in epilogue overlaps other blocks'
//   fma-bound mainloops (disjoint pipes).
// ---------------------------------------------------------------------------
__global__ __launch_bounds__(256, 2) void gemm_fused_kernel(
        int M, int NC,
        uint32_t g1a, uint32_t g1b, uint32_t g2a, uint32_t g2b) {
    __shared__ float As[16][128 + 4];
    __shared__ float Bs[16][128 + 4];
    const int t = threadIdx.x;
    const int tx = t & 15, ty = t >> 4;
    const int bm = blockIdx.y * 128, bn = blockIdx.x * 128;

    u64 acc[8][4];
#pragma unroll
    for (int i = 0; i < 8; i++)
#pragma unroll
        for (int j = 0; j < 4; j++) acc[i][j] = 0ull;

    for (int d0 = 0; d0 < D_DIM; d0 += 16) {
#pragma unroll
        for (int i = 0; i < 2; i++) {
            int idx = t + i * 256;          // 0..511
            int row = idx >> 2;             // 0..127
            int c4  = (idx & 3) << 2;       // 0,4,8,12
            float4 va = *(const float4*)(g_x + (size_t)(bm + row) * D_DIM + d0 + c4);
            As[c4 + 0][row] = va.x; As[c4 + 1][row] = va.y;
            As[c4 + 2][row] = va.z; As[c4 + 3][row] = va.w;
            float4 vb = *(const float4*)(g_cn + (size_t)(bn + row) * D_DIM + d0 + c4);
            Bs[c4 + 0][row] = vb.x; Bs[c4 + 1][row] = vb.y;
            Bs[c4 + 2][row] = vb.z; Bs[c4 + 3][row] = vb.w;
        }
        __syncthreads();
#pragma unroll
        for (int kk = 0; kk < 16; kk++) {
            // rows: ty*4 + {0..3} and 64 + ty*4 + {0..3}
            // cols: tx*4 + {0..3} and 64 + tx*4 + {0..3}
            float a[8], b[8];
            *(float4*)(a)     = *(const float4*)(&As[kk][ty * 4]);
            *(float4*)(a + 4) = *(const float4*)(&As[kk][64 + ty * 4]);
            *(float4*)(b)     = *(const float4*)(&Bs[kk][tx * 4]);
            *(float4*)(b + 4) = *(const float4*)(&Bs[kk][64 + tx * 4]);
            u64 b2[4];
#pragma unroll
            for (int j = 0; j < 4; j++) b2[j] = pk2(b[2 * j], b[2 * j + 1]);
#pragma unroll
            for (int i = 0; i < 8; i++) {
                u64 a2 = pk2(a[i], a[i]);
#pragma unroll
                for (int j = 0; j < 4; j++) acc[i][j] = fma2(a2, b2[j], acc[i][j]);
            }
        }
        __syncthreads();
    }

    // ---- fused epilogue: add gumbel noise (2 draws/elem), write l1/l2
#pragma unroll
    for (int i = 0; i < 8; i++) {
        int row = bm + ((i < 4) ? (ty * 4 + i) : (64 + ty * 4 + i - 4));
        float o[8];
#pragma unroll
        for (int j = 0; j < 4; j++) upk2(acc[i][j], o[2 * j], o[2 * j + 1]);

        int c0 = bn + tx * 4;        // cols c0..c0+3  -> o[0..3]
        int c1 = bn + 64 + tx * 4;   // cols c1..c1+3  -> o[4..7]
        uint32_t base = (uint32_t)row * (uint32_t)NC;

        float v1[8], v2[8];
#pragma unroll
        for (int j = 0; j < 4; j++) {
            uint32_t ctr0 = base + (uint32_t)(c0 + j);
            uint32_t ctr1 = base + (uint32_t)(c1 + j);
            v1[j]     = o[j]     + gumbel_from_bits(tf_bits(g1a, g1b, ctr0));
            v2[j]     = o[j]     + gumbel_from_bits(tf_bits(g2a, g2b, ctr0));
            v1[4 + j] = o[4 + j] + gumbel_from_bits(tf_bits(g1a, g1b, ctr1));
            v2[4 + j] = o[4 + j] + gumbel_from_bits(tf_bits(g2a, g2b, ctr1));
        }
        float* p1 = g_l1 + (size_t)row * NC;
        float* p2 = g_l2 + (size_t)row * NC;
        *(float4*)(p1 + c0) = make_float4(v1[0], v1[1], v1[2], v1[3]);
        *(float4*)(p1 + c1) = make_float4(v1[4], v1[5], v1[6], v1[7]);
        *(float4*)(p2 + c0) = make_float4(v2[0], v2[1], v2[2], v2[3]);
        *(float4*)(p2 + c1) = make_float4(v2[4], v2[5], v2[6], v2[7]);
    }
}

// ---------------------------------------------------------------------------
// Kernel 4 (light): argmax(l1) + softmax(l2) + codebook gather. Memory-bound.
//   One block per row n; thread t handles k = 4t..4t+3 (contiguous float4).
// ---------------------------------------------------------------------------
__global__ void finalize_kernel(const float* __restrict__ cb,
                                float* __restrict__ zq,
                                float* __restrict__ ws,
                                float* __restrict__ idxo,
                                int N, int K) {
    const int T = 256, V = 4;  // K = 1024 = T*V
    int t = threadIdx.x;
    int n = blockIdx.x;

    float l1[V], l2[V];
    *(float4*)l1 = *(const float4*)(g_l1 + (size_t)n * K + t * V);
    *(float4*)l2 = *(const float4*)(g_l2 + (size_t)n * K + t * V);

    __shared__ float sv8[8];
    __shared__ int   si8[8];

    // ---- argmax(l1)  (first-occurrence on exact ties; thread t owns 4t..4t+3)
    float bv = l1[0]; int bi = t * V;
#pragma unroll
    for (int v = 1; v < V; v++) {
        if (l1[v] > bv) { bv = l1[v]; bi = t * V + v; }
    }
    for (int o = 16; o; o >>= 1) {
        float ov = __shfl_down_sync(0xffffffffu, bv, o);
        int   oi = __shfl_down_sync(0xffffffffu, bi, o);
        if (ov > bv || (ov == bv && oi < bi)) { bv = ov; bi = oi; }
    }
    if ((t & 31) == 0) { sv8[t >> 5] = bv; si8[t >> 5] = bi; }
    __syncthreads();
    int best;
    {
        float v0 = sv8[0]; int i0 = si8[0];
#pragma unroll
        for (int w = 1; w < 8; w++)
            if (sv8[w] > v0 || (sv8[w] == v0 && si8[w] < i0)) { v0 = sv8[w]; i0 = si8[w]; }
        best = i0;
    }
    __syncthreads();

    // ---- softmax(l2)
    float m = fmaxf(fmaxf(l2[0], l2[1]), fmaxf(l2[2], l2[3]));
    for (int o = 16; o; o >>= 1) m = fmaxf(m, __shfl_down_sync(0xffffffffu, m, o));
    if ((t & 31) == 0) sv8[t >> 5] = m;
    __syncthreads();
    m = sv8[0];
#pragma unroll
    for (int w = 1; w < 8; w++) m = fmaxf(m, sv8[w]);
    __syncthreads();

    float e[V]; float s = 0.f;
#pragma unroll
    for (int v = 0; v < V; v++) { e[v] = expf(l2[v] - m); s += e[v]; }
    for (int o = 16; o; o >>= 1) s += __shfl_down_sync(0xffffffffu, s, o);
    if ((t & 31) == 0) sv8[t >> 5] = s;
    __syncthreads();
    float tot = sv8[0] + sv8[1] + sv8[2] + sv8[3] + sv8[4] + sv8[5] + sv8[6] + sv8[7];

    float* wrow = ws + (size_t)n * K;
    *(float4*)(wrow + t * V) =
        make_float4(e[0] / tot, e[1] / tot, e[2] / tot, e[3] / tot);

    // ---- z_q = codebook[best], indices
    const float* crow = cb + (size_t)best * D_DIM;
    float* zrow = zq + (size_t)n * D_DIM;
    for (int d = t; d < D_DIM; d += T) zrow[d] = crow[d];
    if (t == 0) idxo[n] = (float)best;
}

// ---------------------------------------------------------------------------
extern "C" void kernel_launch(void* const* d_in, const int* in_sizes, int n_in,
                              void* d_out, int out_size) {
    const float* st = (const float*)d_in[0];
    const float* ad = (const float*)d_in[1];
    const float* cb = (const float*)d_in[2];
    int N = in_sizes[0] / D_DIM;     // 32768
    int K = in_sizes[2] / D_DIM;     // 1024

    float* out  = (float*)d_out;
    float* zq   = out;                              // [N, D]
    float* ws   = out + (size_t)N * D_DIM;          // [N, K]
    float* idxo = ws + (size_t)N * K;               // [N, 1]

    // jax.random.key(42) -> (0,42). Partitionable (fold-like) split:
    //   child i = both output words of threefry((0,42), x0=0, x1=i)
    uint32_t g1a = 0u, g1b = 0u;
    threefry2x32(0u, 42u, g1a, g1b);    // counter 0 -> gk1
    uint32_t g2a = 0u, g2b = 1u;
    threefry2x32(0u, 42u, g2a, g2b);    // counter 1 -> gk2

    norm_cb_kernel<<<K, 128>>>(cb);
    combine_kernel<<<N, 128>>>(st, ad);
    dim3 gg(K / 128, N / 128);
    gemm_fused_kernel<<<gg, 256>>>(N, K, g1a, g1b, g2a, g2b);
    finalize_kernel<<<N, 256>>>(cb, zq, ws, idxo, N, K);
}

// round 5
// speedup vs baseline: 1.1706x; 1.1706x over previous
#include <cuda_runtime.h>
#include <cstdint>
#include <cstddef>

#define DI __device__ __forceinline__
static const int D_DIM = 512;
#define MAXN 32768
#define MAXK 1024
#define NBN  8

extern "C" __device__ float __nv_logf(float);

// Scratch (device globals; no allocation allowed)
__device__ float g_xf[(size_t)MAXN * D_DIM * 2];  // 128MB fragment-packed hi/lo A
__device__ float g_cf[(size_t)MAXK * D_DIM * 2];  //   8MB fragment-packed hi/lo B
__device__ float g_pm[(size_t)MAXN * NBN];
__device__ int   g_pi[(size_t)MAXN * NBN];
__device__ float g_ps[(size_t)MAXN * NBN];

// ---------------------------------------------------------------------------
// Threefry-2x32 (exact JAX, partitionable mode)
// ---------------------------------------------------------------------------
__host__ __device__ inline uint32_t rotl32(uint32_t x, int r) {
    return (x << r) | (x >> (32 - r));
}
__host__ __device__ inline void threefry2x32(uint32_t k0, uint32_t k1,
                                             uint32_t& x0, uint32_t& x1) {
    uint32_t k2 = k0 ^ k1 ^ 0x1BD11BDAu;
    x0 += k0; x1 += k1;
#define TFR(r) { x0 += x1; x1 = rotl32(x1, r); x1 ^= x0; }
    TFR(13) TFR(15) TFR(26) TFR(6)
    x0 += k1; x1 += k2 + 1u;
    TFR(17) TFR(29) TFR(16) TFR(24)
    x0 += k2; x1 += k0 + 2u;
    TFR(13) TFR(15) TFR(26) TFR(6)
    x0 += k0; x1 += k1 + 3u;
    TFR(17) TFR(29) TFR(16) TFR(24)
    x0 += k1; x1 += k2 + 4u;
    TFR(13) TFR(15) TFR(26) TFR(6)
    x0 += k2; x1 += k0 + 5u;
#undef TFR
}
DI uint32_t tf_bits(uint32_t k0, uint32_t k1, uint32_t i) {
    uint32_t x0 = 0u, x1 = i;
    threefry2x32(k0, k1, x0, x1);
    return x0 ^ x1;
}
#define TINYF 1.17549435e-38f
// argmax path: exact bits -> gumbel = -log(-log(u)), precise libdevice log
DI float gumbel_from_bits(uint32_t bits) {
    float u = __uint_as_float((bits >> 9) | 0x3f800000u) - 1.0f;
    float r = fmaxf(TINYF, u + TINYF);
    return -__nv_logf(-__nv_logf(r));
}
// softmax path: exp(g2) = -1/log(u)  (log is 1-ulp relative accurate)
DI float expg_from_bits(uint32_t bits) {
    float u = __uint_as_float((bits >> 9) | 0x3f800000u) - 1.0f;
    float r = fmaxf(TINYF, u + TINYF);
    return -__fdividef(1.0f, __nv_logf(r));
}

// ---------------------------------------------------------------------------
// low-level helpers
// ---------------------------------------------------------------------------
DI uint32_t smem_u32(const void* p) {
    uint32_t a;
    asm("{ .reg .u64 t; cvta.to.shared.u64 t, %1; cvt.u32.u64 %0, t; }"
        : "=r"(a) : "l"(p));
    return a;
}
DI void tf32_split(float x, uint32_t& hi, uint32_t& lo) {
    uint32_t h;
    asm("cvt.rna.tf32.f32 %0, %1;" : "=r"(h) : "f"(x));
    float l = x - __uint_as_float(h);
    uint32_t lr;
    asm("cvt.rna.tf32.f32 %0, %1;" : "=r"(lr) : "f"(l));
    hi = h; lo = lr;
}
DI void cp16(uint32_t saddr, const void* g) {
    asm volatile("cp.async.cg.shared.global [%0], [%1], 16;"
                 :: "r"(saddr), "l"(g) : "memory");
}
#define CP_COMMIT() asm volatile("cp.async.commit_group;" ::: "memory")
#define CP_WAIT0()  asm volatile("cp.async.wait_group 0;" ::: "memory")

DI void lds128(uint32_t* r, uint32_t addr) {
    asm volatile("ld.shared.v4.b32 {%0,%1,%2,%3}, [%4];"
        : "=r"(r[0]), "=r"(r[1]), "=r"(r[2]), "=r"(r[3]) : "r"(addr));
}
// m16n8k8 tf32 MMA (baseline PTX, works on sm_103 non-'a')
DI void mma8(float* d, const uint32_t* a, const uint32_t* b) {
    asm volatile(
        "mma.sync.aligned.m16n8k8.row.col.f32.tf32.tf32.f32 "
        "{%0,%1,%2,%3}, {%4,%5,%6,%7}, {%8,%9}, {%0,%1,%2,%3};"
        : "+f"(d[0]), "+f"(d[1]), "+f"(d[2]), "+f"(d[3])
        : "r"(a[0]), "r"(a[1]), "r"(a[2]), "r"(a[3]), "r"(b[0]), "r"(b[1]));
}

// ---------------------------------------------------------------------------
// Kernel 1: normalize codebook rows, write fragment-packed hi/lo g_cf.
//   g_cf idx = ((nt*64 + kt)*32 + lane)*4 + r, r = [b0h b1h b0l b1l]
//   b0: (k=kt*8+lane%4,     n=nt*8+lane/4);  b1: k+4.
//   One block per 16 rows (2 nt blocks); output region contiguous 64KB.
// ---------------------------------------------------------------------------
__global__ __launch_bounds__(256) void norm_cb_fp(const float* __restrict__ cb) {
    __shared__ float sc[16][516];
    int t = threadIdx.x, lane = t & 31, w = t >> 5;
    int R0 = blockIdx.x * 16;
#pragma unroll
    for (int rr = 0; rr < 2; rr++) {
        int row = 2 * w + rr;
        const float4* rp = (const float4*)(cb + (size_t)(R0 + row) * D_DIM);
        float4 v[4]; float ss = 0.f;
#pragma unroll
        for (int i = 0; i < 4; i++) {
            v[i] = rp[lane + 32 * i];
            ss += v[i].x * v[i].x + v[i].y * v[i].y + v[i].z * v[i].z + v[i].w * v[i].w;
        }
#pragma unroll
        for (int o = 16; o; o >>= 1) ss += __shfl_xor_sync(0xffffffffu, ss, o);
        float inv = 1.0f / fmaxf(sqrtf(ss), 1e-8f);
#pragma unroll
        for (int i = 0; i < 4; i++) {
            float4 q; q.x = v[i].x * inv; q.y = v[i].y * inv;
            q.z = v[i].z * inv; q.w = v[i].w * inv;
            *(float4*)&sc[row][4 * (lane + 32 * i)] = q;
        }
    }
    __syncthreads();
    float* outp = g_cf + (size_t)blockIdx.x * 16384;
#pragma unroll
    for (int q = 0; q < 16; q++) {
        int p = t * 16 + q;                 // position in [0, 4096)
        int nt_l = p >> 11, pp = p & 2047;
        int kt = pp >> 5, ln = pp & 31;
        int nl = nt_l * 8 + (ln >> 2);
        int c  = kt * 8 + (ln & 3);
        uint32_t h0, l0, h1, l1;
        tf32_split(sc[nl][c],     h0, l0);
        tf32_split(sc[nl][c + 4], h1, l1);
        uint4 o; o.x = h0; o.y = h1; o.z = l0; o.w = l1;
        *(uint4*)(outp + (size_t)p * 4) = o;
    }
}

// ---------------------------------------------------------------------------
// Kernel 2: x = 0.5*st/||st|| + 0.5*ad/||ad||, write fragment-packed g_xf.
//   g_xf idx = ((mt*64 + kt)*32 + lane)*8 + r, r = [a0h a1h a2h a3h a0l..a3l]
//   a0:(m=mt*16+lane/4, k=kt*8+lane%4)  a1:(m+8,k)  a2:(m,k+4)  a3:(m+8,k+4)
// ---------------------------------------------------------------------------
__global__ __launch_bounds__(256) void combine_fp(const float* __restrict__ st,
                                                  const float* __restrict__ ad) {
    __shared__ float sx[16][516];
    int t = threadIdx.x, lane = t & 31, w = t >> 5;
    int R0 = blockIdx.x * 16;
#pragma unroll
    for (int rr = 0; rr < 2; rr++) {
        int row = 2 * w + rr;
        const float4* sp = (const float4*)(st + (size_t)(R0 + row) * D_DIM);
        const float4* ap = (const float4*)(ad + (size_t)(R0 + row) * D_DIM);
        float4 sv[4], av[4]; float ss = 0.f, aa = 0.f;
#pragma unroll
        for (int i = 0; i < 4; i++) {
            sv[i] = sp[lane + 32 * i];
            av[i] = ap[lane + 32 * i];
            ss += sv[i].x*sv[i].x + sv[i].y*sv[i].y + sv[i].z*sv[i].z + sv[i].w*sv[i].w;
            aa += av[i].x*av[i].x + av[i].y*av[i].y + av[i].z*av[i].z + av[i].w*av[i].w;
        }
#pragma unroll
        for (int o = 16; o; o >>= 1) {
            ss += __shfl_xor_sync(0xffffffffu, ss, o);
            aa += __shfl_xor_sync(0xffffffffu, aa, o);
        }
        float is = 0.5f / fmaxf(sqrtf(ss), 1e-8f);
        float ia = 0.5f / fmaxf(sqrtf(aa), 1e-8f);
#pragma unroll
        for (int i = 0; i < 4; i++) {
            float4 q;
            q.x = sv[i].x * is + av[i].x * ia;
            q.y = sv[i].y * is + av[i].y * ia;
            q.z = sv[i].z * is + av[i].z * ia;
            q.w = sv[i].w * is + av[i].w * ia;
            *(float4*)&sx[row][4 * (lane + 32 * i)] = q;
        }
    }
    __syncthreads();
    float* outp = g_xf + (size_t)blockIdx.x * 16384;
#pragma unroll
    for (int q = 0; q < 8; q++) {
        int p = t * 8 + q;                  // (kt*32 + lane') in [0, 2048)
        int kt = p >> 5, ln = p & 31;
        int g = ln >> 2, c = kt * 8 + (ln & 3);
        uint32_t h[4], l[4];
        tf32_split(sx[g][c],         h[0], l[0]);
        tf32_split(sx[g + 8][c],     h[1], l[1]);
        tf32_split(sx[g][c + 4],     h[2], l[2]);
        tf32_split(sx[g + 8][c + 4], h[3], l[3]);
        uint4 H; H.x = h[0]; H.y = h[1]; H.z = h[2]; H.w = h[3];
        uint4 L; L.x = l[0]; L.y = l[1]; L.z = l[2]; L.w = l[3];
        *(uint4*)(outp + (size_t)p * 8)     = H;
        *(uint4*)(outp + (size_t)p * 8 + 4) = L;
    }
}

// ---------------------------------------------------------------------------
// Kernel 3: 3xTF32 mma.sync GEMM (128x128 tile, BK=32) + fused gumbel epilogue.
//   8 warps = 4(M) x 2(N); warp tile 32x64; acc 16 tiles x 4 regs.
//   cp.async single-stage SMEM (A 32KB + B 32KB); 2 CTAs/SM overlap
//   epilogue (alu/fma/mufu) with co-resident CTA's MMA (tensor/LDS).
// ---------------------------------------------------------------------------
__global__ __launch_bounds__(256, 2) void gemm_mma(
        float* __restrict__ ws,
        uint32_t k1a, uint32_t k1b, uint32_t k2a, uint32_t k2b) {
    extern __shared__ char smem[];
    const uint32_t sa = smem_u32(smem);
    const uint32_t sb = sa + 32768;
    const int t = threadIdx.x, lane = t & 31, wid = t >> 5;
    const int wm = wid >> 1, wn = wid & 1;
    const int mtb = blockIdx.y * 8, ntb = blockIdx.x * 16;
    const int bm = blockIdx.y * 128, bn = blockIdx.x * 128;

    float acc[16][4];
#pragma unroll
    for (int i = 0; i < 16; i++)
#pragma unroll
        for (int j = 0; j < 4; j++) acc[i][j] = 0.f;

    for (int c = 0; c < 16; c++) {
        int kt0 = c * 4;
#pragma unroll
        for (int i = 0; i < 8; i++) {          // A: 2048 x 16B
            int u = t + i * 256;
            int blk = u >> 6, off = u & 63;
            const float* g = g_xf
                + ((size_t)(mtb + (blk >> 2)) * 64 + kt0 + (blk & 3)) * 256
                + off * 4;
            cp16(sa + blk * 1024 + off * 16, g);
        }
#pragma unroll
        for (int i = 0; i < 8; i++) {          // B: 2048 x 16B
            int u = t + i * 256;
            int blk = u >> 5, off = u & 31;
            const float* g = g_cf
                + ((size_t)(ntb + (blk >> 2)) * 64 + kt0 + (blk & 3)) * 128
                + off * 4;
            cp16(sb + blk * 512 + off * 16, g);
        }
        CP_COMMIT(); CP_WAIT0();
        __syncthreads();
#pragma unroll
        for (int ktl = 0; ktl < 4; ktl++) {
            uint32_t ah[2][4], al[2][4];
#pragma unroll
            for (int m = 0; m < 2; m++) {
                uint32_t base = sa + (((wm * 2 + m) * 4 + ktl) * 32 + lane) * 32;
                lds128(ah[m], base);
                lds128(al[m], base + 16);
            }
#pragma unroll
            for (int g2 = 0; g2 < 2; g2++) {
                uint32_t bh[4][2], bl[4][2];
#pragma unroll
                for (int n4 = 0; n4 < 4; n4++) {
                    uint32_t baddr = sb +
                        (((wn * 8 + g2 * 4 + n4) * 4 + ktl) * 32 + lane) * 16;
                    uint32_t bv[4];
                    lds128(bv, baddr);
                    bh[n4][0] = bv[0]; bh[n4][1] = bv[1];
                    bl[n4][0] = bv[2]; bl[n4][1] = bv[3];
                }
#pragma unroll
                for (int m = 0; m < 2; m++)
#pragma unroll
                    for (int n4 = 0; n4 < 4; n4++) {
                        float* A = acc[m * 8 + g2 * 4 + n4];
                        mma8(A, ah[m], bh[n4]);
                        mma8(A, ah[m], bl[n4]);
                        mma8(A, al[m], bh[n4]);
                    }
            }
        }
        __syncthreads();
    }

    // ---- fused epilogue: gumbel + per-row partial argmax/sum, exp into ws
    float rmax[4], rsum[4]; int ridx[4];
#pragma unroll
    for (int m = 0; m < 2; m++)
#pragma unroll
    for (int h = 0; h < 2; h++) {
        int e = m * 2 + h;
        int grow = bm + wm * 32 + m * 16 + h * 8 + (lane >> 2);
        int colb = bn + wn * 64 + (lane & 3) * 2;
        float bmax = -3.4e38f; int bidx = 0; float bsum = 0.f;
        float* wrow = ws + (size_t)grow * 1024;
        uint32_t ctrb = (uint32_t)grow * 1024u;
#pragma unroll
        for (int n = 0; n < 8; n++) {
            int cc = colb + n * 8;
            float s0 = acc[m * 8 + n][h * 2];
            float s1 = acc[m * 8 + n][h * 2 + 1];
            uint32_t i0 = ctrb + (uint32_t)cc;
            float v1a = s0 + gumbel_from_bits(tf_bits(k1a, k1b, i0));
            float v1b = s1 + gumbel_from_bits(tf_bits(k1a, k1b, i0 + 1u));
            if (v1a > bmax) { bmax = v1a; bidx = cc; }
            if (v1b > bmax) { bmax = v1b; bidx = cc + 1; }
            float p0 = __expf(s0) * expg_from_bits(tf_bits(k2a, k2b, i0));
            float p1 = __expf(s1) * expg_from_bits(tf_bits(k2a, k2b, i0 + 1u));
            bsum += p0 + p1;
            *(float2*)(wrow + cc) = make_float2(p0, p1);
        }
#pragma unroll
        for (int o = 1; o <= 2; o <<= 1) {
            float om = __shfl_xor_sync(0xffffffffu, bmax, o);
            int   oi = __shfl_xor_sync(0xffffffffu, bidx, o);
            float os = __shfl_xor_sync(0xffffffffu, bsum, o);
            if (om > bmax || (om == bmax && oi < bidx)) { bmax = om; bidx = oi; }
            bsum += os;
        }
        rmax[e] = bmax; ridx[e] = bidx; rsum[e] = bsum;
    }

    float* rm = (float*)(smem + 65536);
    int*   ri = (int*)  (smem + 65536 + 512);
    float* rs = (float*)(smem + 65536 + 1024);
    if (wn == 1 && (lane & 3) == 0) {
#pragma unroll
        for (int e = 0; e < 4; e++) {
            int rl = wm * 32 + (e >> 1) * 16 + (e & 1) * 8 + (lane >> 2);
            rm[rl] = rmax[e]; ri[rl] = ridx[e]; rs[rl] = rsum[e];
        }
    }
    __syncthreads();
    if (wn == 0 && (lane & 3) == 0) {
#pragma unroll
        for (int e = 0; e < 4; e++) {
            int rl = wm * 32 + (e >> 1) * 16 + (e & 1) * 8 + (lane >> 2);
            float om = rm[rl]; int oi = ri[rl]; float os = rs[rl];
            float bmv = rmax[e]; int biv = ridx[e];
            if (om > bmv || (om == bmv && oi < biv)) { bmv = om; biv = oi; }
            size_t pidx = (size_t)(bm + rl) * NBN + blockIdx.x;
            g_pm[pidx] = bmv; g_pi[pidx] = biv; g_ps[pidx] = rsum[e] + os;
        }
    }
}

// ---------------------------------------------------------------------------
// Kernel 4: reduce partials per row, normalize ws, gather z_q, indices.
// ---------------------------------------------------------------------------
__global__ void finalize_kernel(const float* __restrict__ cb,
                                float* __restrict__ zq,
                                float* __restrict__ ws,
                                float* __restrict__ idxo) {
    int n = blockIdx.x, t = threadIdx.x;
    __shared__ int   s_best;
    __shared__ float s_inv;
    if (t == 0) {
        float bm = g_pm[(size_t)n * NBN]; int bi = g_pi[(size_t)n * NBN];
        float sum = g_ps[(size_t)n * NBN];
#pragma unroll
        for (int j = 1; j < NBN; j++) {
            float m = g_pm[(size_t)n * NBN + j];
            int   i = g_pi[(size_t)n * NBN + j];
            if (m > bm || (m == bm && i < bi)) { bm = m; bi = i; }
            sum += g_ps[(size_t)n * NBN + j];
        }
        s_best = bi;
        s_inv  = 1.0f / sum;
    }
    __syncthreads();
    int best = s_best; float inv = s_inv;

    float4* wrow = (float4*)(ws + (size_t)n * 1024);
    float4 v = wrow[t];
    v.x *= inv; v.y *= inv; v.z *= inv; v.w *= inv;
    wrow[t] = v;

    if (t < 128) {
        float4 c = *(const float4*)(cb + (size_t)best * D_DIM + t * 4);
        *(float4*)(zq + (size_t)n * D_DIM + t * 4) = c;
    }
    if (t == 0) idxo[n] = (float)best;
}

// ---------------------------------------------------------------------------
extern "C" void kernel_launch(void* const* d_in, const int* in_sizes, int n_in,
                              void* d_out, int out_size) {
    const float* st = (const float*)d_in[0];
    const float* ad = (const float*)d_in[1];
    const float* cb = (const float*)d_in[2];
    int N = in_sizes[0] / D_DIM;     // 32768
    int K = in_sizes[2] / D_DIM;     // 1024

    float* out  = (float*)d_out;
    float* zq   = out;                              // [N, D]
    float* ws   = out + (size_t)N * D_DIM;          // [N, K]
    float* idxo = ws + (size_t)N * K;               // [N, 1]

    // jax.random.key(42) -> (0,42); partitionable fold split
    uint32_t g1a = 0u, g1b = 0u;
    threefry2x32(0u, 42u, g1a, g1b);    // counter 0 -> gk1
    uint32_t g2a = 0u, g2b = 1u;
    threefry2x32(0u, 42u, g2a, g2b);    // counter 1 -> gk2

    static int smem_set = 0;
    if (!smem_set) {
        cudaFuncSetAttribute(gemm_mma,
            cudaFuncAttributeMaxDynamicSharedMemorySize, 65536 + 1536);
        smem_set = 1;
    }

    norm_cb_fp<<<K / 16, 256>>>(cb);
    combine_fp<<<N / 16, 256>>>(st, ad);
    dim3 gg(K / 128, N / 128);
    gemm_mma<<<gg, 256, 65536 + 1536>>>(ws, g1a, g1b, g2a, g2b);
    finalize_kernel<<<N, 256>>>(cb, zq, ws, idxo);
}